// round 4
// baseline (speedup 1.0000x reference)
#include <cuda_runtime.h>
#include <stdint.h>

// Transducer loss: unnormalized linear-domain f64 recurrence.
// K1: p_hat = 2^(x/ln2) (streaming map) + per-row log2(rowsum)
// K2: per-batch sum of log2(rowsum)  (normalization correction)
// K3: S_{t+2}[j] = A*S[j] + B*S[j-1] + C*S[j-2] in f64, one warp/batch
// K4: deterministic mean

#define INV_LN2 1.44269504088896340736f
#define LN2_D   0.6931471805599453094172321

static constexpr int B  = 128;
static constexpr int T  = 2000;
static constexpr int C  = 62;
static constexpr int L  = 256;
static constexpr int RL = 8;            // labels per lane

__device__ float g_prob[B * T * C + 16 * C];  // raw 2^(x/ln2), padded for prefetch overshoot
__device__ float g_lgs[B * T];                // log2 of per-row sum
__device__ float g_lcorr[B];                  // per-batch sum of g_lgs
__device__ float g_bloss[B];

static __device__ __forceinline__ float ex2f(float x) {
    float y; asm("ex2.approx.ftz.f32 %0, %1;" : "=f"(y) : "f"(x)); return y;
}
static __device__ __forceinline__ float lg2f(float x) {
    float y; asm("lg2.approx.ftz.f32 %0, %1;" : "=f"(y) : "f"(x)); return y;
}

// ---------------------------------------------------------------------------
// K1: streaming map + fused rowsums. 256 threads handle 32 rows (1984 floats).
// ---------------------------------------------------------------------------
__global__ __launch_bounds__(256) void prob_kernel(const float* __restrict__ x) {
    __shared__ float sp[32 * C];
    const long base = (long)blockIdx.x * (32 * C);

    for (int i = threadIdx.x; i < 32 * C; i += 256) {
        const float p = ex2f(__ldg(x + base + i) * INV_LN2);
        g_prob[base + i] = p;
        sp[i] = p;
    }
    __syncthreads();

    const int r = threadIdx.x >> 3;      // row 0..31
    const int k = threadIdx.x & 7;       // 8 threads per row
    float s = 0.f;
    const int off = r * C + k * 8;
#pragma unroll
    for (int i = 0; i < 8; i++)
        if (k * 8 + i < C) s += sp[off + i];
    s += __shfl_xor_sync(0xffffffffu, s, 4);
    s += __shfl_xor_sync(0xffffffffu, s, 2);
    s += __shfl_xor_sync(0xffffffffu, s, 1);
    if (k == 0) g_lgs[blockIdx.x * 32 + r] = lg2f(s);
}

// ---------------------------------------------------------------------------
// K2: per-batch normalization correction (deterministic fixed-order sums).
// ---------------------------------------------------------------------------
__global__ __launch_bounds__(256) void corr_kernel() {
    const int b = blockIdx.x;
    float s = 0.f;
    for (int i = threadIdx.x; i < T; i += 256) s += g_lgs[b * T + i];
    __shared__ float sm[256];
    sm[threadIdx.x] = s;
    __syncthreads();
    for (int o = 128; o; o >>= 1) {
        if (threadIdx.x < o) sm[threadIdx.x] += sm[threadIdx.x + o];
        __syncthreads();
    }
    if (threadIdx.x == 0) g_lcorr[b] = sm[0];
}

// ---------------------------------------------------------------------------
// K3: the recurrence. One warp per batch, f64 state, fused 2-step updates.
// ---------------------------------------------------------------------------
static __device__ __forceinline__ void step2(double S[RL], float* Pt, float* Pt1,
                                             const float* const q[RL], int pf_off,
                                             int lane) {
    // neighbor values from lane-1 (old state / old probs)
    float  pm1 = __shfl_up_sync(0xffffffffu, Pt[RL - 1], 1);
    double s7  = __shfl_up_sync(0xffffffffu, S[RL - 1], 1);
    double s6  = __shfl_up_sync(0xffffffffu, S[RL - 2], 1);
    if (lane == 0) { pm1 = 0.f; s7 = 0.0; s6 = 0.0; }

    float A[RL], Bc[RL], Cc[RL];
#pragma unroll
    for (int j = 0; j < RL; j++) {
        A[j] = Pt[j] * Pt1[j];
        const float pl = (j == 0) ? pm1 : Pt[j - 1];
        Cc[j] = pl * Pt1[j];
        Bc[j] = A[j] + Cc[j];
    }
    // descending in-place: reads of S[j-1], S[j-2] are pre-update values
#pragma unroll
    for (int j = RL - 1; j >= 2; j--)
        S[j] = fma((double)A[j], S[j],
                   fma((double)Bc[j], S[j - 1], (double)Cc[j] * S[j - 2]));
    S[1] = fma((double)A[1], S[1], fma((double)Bc[1], S[0], (double)Cc[1] * s7));
    S[0] = fma((double)A[0], S[0], fma((double)Bc[0], s7, (double)Cc[0] * s6));

    // refill this buffer for 3 iterations ahead
#pragma unroll
    for (int j = 0; j < RL; j++) {
        Pt[j]  = __ldg(q[j] + pf_off);
        Pt1[j] = __ldg(q[j] + pf_off + C);
    }
}

__global__ __launch_bounds__(32, 1) void recur_kernel(const int* __restrict__ tg) {
    const int b = blockIdx.x;
    const int lane = threadIdx.x;

    const float* prow = g_prob + (long)b * T * C;
    const float* q[RL];
#pragma unroll
    for (int j = 0; j < RL; j++) {
        const int tc = __ldg(tg + b * L + lane * RL + j);
        q[j] = prow + tc;
    }

    // t = 0 init (unnormalized emission)
    double S[RL];
#pragma unroll
    for (int j = 0; j < RL; j++) S[j] = 0.0;
    if (lane == 0) S[0] = (double)__ldg(q[0]);

    // t = 1 single step
    {
        float p1[RL];
#pragma unroll
        for (int j = 0; j < RL; j++) p1[j] = __ldg(q[j] + C);
        double c7 = __shfl_up_sync(0xffffffffu, S[RL - 1], 1);
        if (lane == 0) c7 = 0.0;
#pragma unroll
        for (int j = RL - 1; j >= 1; j--) S[j] = (S[j] + S[j - 1]) * (double)p1[j];
        S[0] = (S[0] + c7) * (double)p1[0];
    }

    // preload 3 double-step buffers: (t,t+1) = (2,3), (4,5), (6,7)
    float PtA[RL], Pt1A[RL], PtB[RL], Pt1B[RL], PtC[RL], Pt1C[RL];
#pragma unroll
    for (int j = 0; j < RL; j++) {
        PtA[j] = __ldg(q[j] + 2 * C);  Pt1A[j] = __ldg(q[j] + 3 * C);
        PtB[j] = __ldg(q[j] + 4 * C);  Pt1B[j] = __ldg(q[j] + 5 * C);
        PtC[j] = __ldg(q[j] + 6 * C);  Pt1C[j] = __ldg(q[j] + 7 * C);
    }

    int base = 0;
    int off = 2 * C;   // element offset of the current iteration's first step

    // 999 double-steps (t = 2 .. 1999), 333 macro-iterations of 3
    for (int mi = 0; mi < 333; mi++) {
        step2(S, PtA, Pt1A, q, off + 6 * C, lane); off += 2 * C;
        step2(S, PtB, Pt1B, q, off + 6 * C, lane); off += 2 * C;
        step2(S, PtC, Pt1C, q, off + 6 * C, lane); off += 2 * C;

        // exact power-of-two renorm: pin warp max near 2^600
        int e = 0;
#pragma unroll
        for (int j = 0; j < RL; j++) e = max(e, __double2hiint(S[j]));
#pragma unroll
        for (int o = 16; o; o >>= 1) e = max(e, __shfl_xor_sync(0xffffffffu, e, o));
        const int ex = (e >> 20) & 0x7ff;                 // biased exponent of max
        const double sc = __hiloint2double((2646 - ex) << 20, 0);  // 2^(600-(ex-1023))
#pragma unroll
        for (int j = 0; j < RL; j++) S[j] *= sc;
        base += ex - 1623;
    }

    if (lane == 31) {
        const double alpha2 = log2(S[RL - 1]) + (double)base;       // raw log2 alpha
        const double loss = ((double)g_lcorr[b] - alpha2) * LN2_D;  // normalize + nats
        g_bloss[b] = (float)loss;
    }
}

// ---------------------------------------------------------------------------
// K4: deterministic mean over the batch.
// ---------------------------------------------------------------------------
__global__ __launch_bounds__(128) void reduce_kernel(float* __restrict__ out) {
    const int i = threadIdx.x;
    float v = g_bloss[i];
#pragma unroll
    for (int o = 16; o; o >>= 1) v += __shfl_xor_sync(0xffffffffu, v, o);
    __shared__ float ws[4];
    if ((i & 31) == 0) ws[i >> 5] = v;
    __syncthreads();
    if (i == 0) out[0] = (ws[0] + ws[1] + ws[2] + ws[3]) * (1.0f / (float)B);
}

// ---------------------------------------------------------------------------
extern "C" void kernel_launch(void* const* d_in, const int* in_sizes, int n_in,
                              void* d_out, int out_size) {
    const float* x = (const float*)d_in[0];   // [B, T, C] float32
    const int* tg = (const int*)d_in[1];      // [B, L] int32
    float* out = (float*)d_out;

    (void)in_sizes; (void)n_in; (void)out_size;

    prob_kernel<<<(B * T) / 32, 256>>>(x);
    corr_kernel<<<B, 256>>>();
    recur_kernel<<<B, 32>>>(tg);
    reduce_kernel<<<1, 128>>>(out);
}

// round 7
// speedup vs baseline: 7.8635x; 7.8635x over previous
#include <cuda_runtime.h>
#include <stdint.h>

// Transducer loss: unnormalized linear-domain fp32 recurrence with per-lane
// power-of-two exponent bases. Lane max pinned at 2^0; base clamped to within
// 48 units below left neighbor (prevents carry-conversion overflow); exact
// two-stage power-of-2 rescales; packed f32x2 math.

#define INV_LN2 1.44269504088896340736f
#define LN2_F   0.69314718055994530942f

static constexpr int B  = 128;
static constexpr int T  = 2000;
static constexpr int C  = 62;
static constexpr int L  = 256;

typedef unsigned long long ull;
typedef unsigned int u32;

__device__ float g_prob[B * T * C + 16 * C];  // raw 2^(x/ln2), padded
__device__ float g_lgs[B * T];                // log2 of per-row sum
__device__ float g_lcorr[B];                  // per-batch sum of g_lgs
__device__ float g_bloss[B];

static __device__ __forceinline__ float ex2f(float x) {
    float y; asm("ex2.approx.ftz.f32 %0, %1;" : "=f"(y) : "f"(x)); return y;
}
static __device__ __forceinline__ float lg2f(float x) {
    float y; asm("lg2.approx.ftz.f32 %0, %1;" : "=f"(y) : "f"(x)); return y;
}
static __device__ __forceinline__ ull pk(float lo, float hi) {
    ull r; asm("mov.b64 %0, {%1, %2};" : "=l"(r) : "f"(lo), "f"(hi)); return r;
}
static __device__ __forceinline__ void upk(ull v, float& lo, float& hi) {
    asm("mov.b64 {%0, %1}, %2;" : "=f"(lo), "=f"(hi) : "l"(v));
}
static __device__ __forceinline__ ull add2(ull a, ull b) {
    ull r; asm("add.rn.f32x2 %0, %1, %2;" : "=l"(r) : "l"(a), "l"(b)); return r;
}
static __device__ __forceinline__ ull mul2(ull a, ull b) {
    ull r; asm("mul.rn.f32x2 %0, %1, %2;" : "=l"(r) : "l"(a), "l"(b)); return r;
}
static __device__ __forceinline__ float p2f(int e) {   // 2^e, e in [-126,127]
    return __uint_as_float((u32)(127 + e) << 23);
}

// ---------------------------------------------------------------------------
// K1: streaming map + fused rowsums. 256 threads handle 32 rows.
// ---------------------------------------------------------------------------
__global__ __launch_bounds__(256) void prob_kernel(const float* __restrict__ x) {
    __shared__ float sp[32 * C];
    const long base = (long)blockIdx.x * (32 * C);

    for (int i = threadIdx.x; i < 32 * C; i += 256) {
        const float p = ex2f(__ldg(x + base + i) * INV_LN2);
        g_prob[base + i] = p;
        sp[i] = p;
    }
    __syncthreads();

    const int r = threadIdx.x >> 3;
    const int k = threadIdx.x & 7;
    float s = 0.f;
    const int off = r * C + k * 8;
#pragma unroll
    for (int i = 0; i < 8; i++)
        if (k * 8 + i < C) s += sp[off + i];
    s += __shfl_xor_sync(0xffffffffu, s, 4);
    s += __shfl_xor_sync(0xffffffffu, s, 2);
    s += __shfl_xor_sync(0xffffffffu, s, 1);
    if (k == 0) g_lgs[blockIdx.x * 32 + r] = lg2f(s);
}

// ---------------------------------------------------------------------------
// K2: per-batch normalization correction.
// ---------------------------------------------------------------------------
__global__ __launch_bounds__(256) void corr_kernel() {
    const int b = blockIdx.x;
    float s = 0.f;
    for (int i = threadIdx.x; i < T; i += 256) s += g_lgs[b * T + i];
    __shared__ float sm[256];
    sm[threadIdx.x] = s;
    __syncthreads();
    for (int o = 128; o; o >>= 1) {
        if (threadIdx.x < o) sm[threadIdx.x] += sm[threadIdx.x + o];
        __syncthreads();
    }
    if (threadIdx.x == 0) g_lcorr[b] = sm[0];
}

// ---------------------------------------------------------------------------
// K3: the recurrence. One warp per batch. State v0..v3 = labels 8L..8L+7.
// ---------------------------------------------------------------------------
__global__ __launch_bounds__(32, 1) void recur_kernel(const int* __restrict__ tg) {
    const int b = blockIdx.x;
    const int lane = threadIdx.x;

    const float* prow = g_prob + (long)b * T * C;
    const float* q[8];
#pragma unroll
    for (int j = 0; j < 8; j++)
        q[j] = prow + __ldg(tg + b * L + lane * 8 + j);

    ull PP[8][4];
#pragma unroll
    for (int k = 0; k < 8; k++)
#pragma unroll
        for (int p = 0; p < 4; p++)
            PP[k][p] = pk(__ldg(q[2 * p] + k * C), __ldg(q[2 * p + 1] + k * C));

    ull v0 = 0ull, v1 = 0ull, v2 = 0ull, v3 = 0ull;
    if (lane == 0) {
        float p0, ph; upk(PP[0][0], p0, ph);
        v0 = pk(p0, 0.f);
    }
#pragma unroll
    for (int p = 0; p < 4; p++)
        PP[0][p] = pk(__ldg(q[2 * p] + 8 * C), __ldg(q[2 * p + 1] + 8 * C));

    int base = 0;               // true = rep * 2^base, per lane
    float c1 = 1.f, c2 = 1.f;   // carry rescale 2^(base_{l-1}-base_l), split

#define STEP(slot, refill_off, do_refill)                                     \
    do {                                                                       \
        float s7lo, s7hi; upk(v3, s7lo, s7hi);                                 \
        float cr = __shfl_up_sync(0xffffffffu, s7hi, 1);                       \
        cr = (lane == 0) ? 0.f : cr * c1 * c2;                                 \
        float a0, a1, b0x, b1x, c0x, c1x;                                      \
        upk(v0, a0, a1); upk(v1, b0x, b1x); upk(v2, c0x, c1x);                 \
        ull w0 = pk(cr,  a0);                                                  \
        ull w1 = pk(a1,  b0x);                                                 \
        ull w2 = pk(b1x, c0x);                                                 \
        ull w3 = pk(c1x, s7lo);                                                \
        v0 = mul2(add2(v0, w0), PP[slot][0]);                                  \
        v1 = mul2(add2(v1, w1), PP[slot][1]);                                  \
        v2 = mul2(add2(v2, w2), PP[slot][2]);                                  \
        v3 = mul2(add2(v3, w3), PP[slot][3]);                                  \
        if (do_refill) {                                                       \
            PP[slot][0] = pk(__ldg(q[0] + (refill_off)), __ldg(q[1] + (refill_off))); \
            PP[slot][1] = pk(__ldg(q[2] + (refill_off)), __ldg(q[3] + (refill_off))); \
            PP[slot][2] = pk(__ldg(q[4] + (refill_off)), __ldg(q[5] + (refill_off))); \
            PP[slot][3] = pk(__ldg(q[6] + (refill_off)), __ldg(q[7] + (refill_off))); \
        }                                                                      \
    } while (0)

// Renorm: pin lane max near 2^0; base clamped to >= (left base - 48);
// zero lanes adopt left base. Scale applied as two exact pow2 multiplies.
#define RENORM()                                                               \
    do {                                                                       \
        float xa, xb; u32 m;                                                   \
        upk(v0, xa, xb); m = max(__float_as_uint(xa), __float_as_uint(xb));    \
        upk(v1, xa, xb); m = max(m, max(__float_as_uint(xa), __float_as_uint(xb))); \
        upk(v2, xa, xb); m = max(m, max(__float_as_uint(xa), __float_as_uint(xb))); \
        upk(v3, xa, xb); m = max(m, max(__float_as_uint(xa), __float_as_uint(xb))); \
        int e = (int)(m >> 23);                                                \
        int d = min(127, max(-126, 127 - e));                                  \
        const int tb = (m == 0u) ? base : (base - d);                          \
        const int bp = __shfl_up_sync(0xffffffffu, tb, 1);                     \
        int nb = tb;                                                           \
        if (lane > 0) nb = (m == 0u) ? bp : max(tb, bp - 48);                  \
        const int sh = base - nb;                                              \
        const int s1 = min(127, max(-126, sh));                                \
        const int s2 = min(127, max(-126, sh - s1));                           \
        const float f1 = p2f(s1), f2 = p2f(s2);                                \
        const ull z1 = pk(f1, f1), z2 = pk(f2, f2);                            \
        v0 = mul2(mul2(v0, z1), z2); v1 = mul2(mul2(v1, z1), z2);              \
        v2 = mul2(mul2(v2, z1), z2); v3 = mul2(mul2(v3, z1), z2);              \
        base = nb;                                                             \
        const int bpf = __shfl_up_sync(0xffffffffu, base, 1);                  \
        int diff = (lane == 0) ? 0 : (bpf - base);                             \
        int d1 = diff >> 1;                                                    \
        int d2 = diff - d1;                                                    \
        d1 = min(126, max(-126, d1)); d2 = min(126, max(-126, d2));            \
        c1 = p2f(d1); c2 = p2f(d2);                                            \
    } while (0)

    // Main: 249 blocks of 8 steps, t = 1 .. 1992.
    for (int blk = 0; blk < 249; blk++) {
#pragma unroll
        for (int kk = 0; kk < 8; kk++) {
            const int slot = (kk + 1) & 7;
            STEP(slot, (kk + 9) * C, true);
            if (kk == 3 || kk == 7) RENORM();
        }
#pragma unroll
        for (int j = 0; j < 8; j++) q[j] += 8 * C;
    }

    // Tail: t = 1993 .. 1999 (7 steps).
#pragma unroll
    for (int kk = 0; kk < 7; kk++) {
        STEP(kk + 1, 0, false);
        if (kk == 3) RENORM();
    }

    if (lane == 31) {
        float s7lo, s7hi; upk(v3, s7lo, s7hi);
        const float alpha2 = lg2f(s7hi) + (float)base;           // raw log2 alpha
        g_bloss[b] = (g_lcorr[b] - alpha2) * LN2_F;              // normalize, nats
    }
#undef STEP
#undef RENORM
}

// ---------------------------------------------------------------------------
// K4: deterministic mean over the batch.
// ---------------------------------------------------------------------------
__global__ __launch_bounds__(128) void reduce_kernel(float* __restrict__ out) {
    const int i = threadIdx.x;
    float v = g_bloss[i];
#pragma unroll
    for (int o = 16; o; o >>= 1) v += __shfl_xor_sync(0xffffffffu, v, o);
    __shared__ float ws[4];
    if ((i & 31) == 0) ws[i >> 5] = v;
    __syncthreads();
    if (i == 0) out[0] = (ws[0] + ws[1] + ws[2] + ws[3]) * (1.0f / (float)B);
}

// ---------------------------------------------------------------------------
extern "C" void kernel_launch(void* const* d_in, const int* in_sizes, int n_in,
                              void* d_out, int out_size) {
    const float* x = (const float*)d_in[0];   // [B, T, C] float32
    const int* tg = (const int*)d_in[1];      // [B, L] int32
    float* out = (float*)d_out;

    (void)in_sizes; (void)n_in; (void)out_size;

    prob_kernel<<<(B * T) / 32, 256>>>(x);
    corr_kernel<<<B, 256>>>();
    recur_kernel<<<B, 32>>>(tg);
    reduce_kernel<<<1, 128>>>(out);
}

// round 8
// speedup vs baseline: 8.0401x; 1.0225x over previous
#include <cuda_runtime.h>
#include <stdint.h>

// Transducer loss: unnormalized linear-domain fp32 recurrence, scalar math
// (no inline-asm packing), per-lane power-of-two exponent bases with
// bounded-diff clamp (proven in R7). K1 vectorized; corr fused into K2.

#define INV_LN2 1.44269504088896340736f
#define LN2_F   0.69314718055994530942f

static constexpr int B  = 128;
static constexpr int T  = 2000;
static constexpr int C  = 62;
static constexpr int L  = 256;

typedef unsigned int u32;

__device__ float g_prob[B * T * C + 16 * C];  // raw 2^(x/ln2), padded
__device__ float g_lgs[B * T];                // log2 of per-row sum
__device__ float g_bloss[B];

static __device__ __forceinline__ float ex2f(float x) {
    float y; asm("ex2.approx.ftz.f32 %0, %1;" : "=f"(y) : "f"(x)); return y;
}
static __device__ __forceinline__ float lg2f(float x) {
    float y; asm("lg2.approx.ftz.f32 %0, %1;" : "=f"(y) : "f"(x)); return y;
}
static __device__ __forceinline__ float p2f(int e) {   // 2^e, e in [-126,127]
    return __uint_as_float((u32)(127 + e) << 23);
}

// ---------------------------------------------------------------------------
// K1: streaming map + fused rowsums, float4 vectorized.
// One block = 32 rows = 1984 floats = 496 float4 (16B-aligned: 32*C*4 = 7936B).
// ---------------------------------------------------------------------------
__global__ __launch_bounds__(256) void prob_kernel(const float* __restrict__ x) {
    __shared__ float sp[32 * C];
    const long base = (long)blockIdx.x * (32 * C);
    const float4* xv = (const float4*)(x + base);
    float4* pv = (float4*)(g_prob + base);

#pragma unroll
    for (int it = 0; it < 2; it++) {
        const int i = threadIdx.x + it * 256;
        if (i < (32 * C) / 4) {
            const float4 v = __ldg(xv + i);
            float4 p;
            p.x = ex2f(v.x * INV_LN2);
            p.y = ex2f(v.y * INV_LN2);
            p.z = ex2f(v.z * INV_LN2);
            p.w = ex2f(v.w * INV_LN2);
            pv[i] = p;
            *(float4*)(sp + 4 * i) = p;
        }
    }
    __syncthreads();

    const int r = threadIdx.x >> 3;      // row 0..31
    const int k = threadIdx.x & 7;       // 8 threads per row
    float s = 0.f;
    const int off = r * C + k * 8;
#pragma unroll
    for (int i = 0; i < 8; i++)
        if (k * 8 + i < C) s += sp[off + i];
    s += __shfl_xor_sync(0xffffffffu, s, 4);
    s += __shfl_xor_sync(0xffffffffu, s, 2);
    s += __shfl_xor_sync(0xffffffffu, s, 1);
    if (k == 0) g_lgs[blockIdx.x * 32 + r] = lg2f(s);
}

// ---------------------------------------------------------------------------
// K2: the recurrence. One warp per batch, scalar fp32, per-lane exponent base.
// S[0..7] = labels 8*lane .. 8*lane+7. Normalization correction fused.
// ---------------------------------------------------------------------------
__global__ __launch_bounds__(32, 1) void recur_kernel(const int* __restrict__ tg) {
    const int b = blockIdx.x;
    const int lane = threadIdx.x;

    // ---- fused normalization-correction partial sum (off critical path) ----
    float corr = 0.f;
    {
        const float4* lgv = (const float4*)(g_lgs + b * T);   // 500 float4
#pragma unroll 4
        for (int i = lane; i < T / 4; i += 32) {
            const float4 v = __ldg(lgv + i);
            corr += (v.x + v.y) + (v.z + v.w);
        }
    }

    const float* prow = g_prob + (long)b * T * C;
    const float* q[8];
#pragma unroll
    for (int j = 0; j < 8; j++)
        q[j] = prow + __ldg(tg + b * L + lane * 8 + j);

    // Prefetch slots: slot k holds probs for time t with t%8 == k.
    float P[8][8];
#pragma unroll
    for (int k = 0; k < 8; k++)
#pragma unroll
        for (int j = 0; j < 8; j++)
            P[k][j] = __ldg(q[j] + k * C);

    float S[8];
#pragma unroll
    for (int j = 0; j < 8; j++) S[j] = 0.f;
    if (lane == 0) S[0] = P[0][0];          // t = 0 init

    // slot 0 consumed -> refill with t = 8
#pragma unroll
    for (int j = 0; j < 8; j++) P[0][j] = __ldg(q[j] + 8 * C);

    int base = 0;                            // true = S * 2^base, per lane
    float c1 = (lane == 0) ? 0.f : 1.f;      // carry rescale (lane0 mask folded)
    float c2 = 1.f;

#define STEP(slot, refill_off, do_refill)                                      \
    do {                                                                        \
        float cr = __shfl_up_sync(0xffffffffu, S[7], 1);                        \
        cr = cr * c1 * c2;                                                      \
        _Pragma("unroll")                                                       \
        for (int j = 7; j >= 1; j--) S[j] = (S[j] + S[j - 1]) * P[slot][j];     \
        S[0] = (S[0] + cr) * P[slot][0];                                        \
        if (do_refill) {                                                        \
            _Pragma("unroll")                                                   \
            for (int j = 0; j < 8; j++) P[slot][j] = __ldg(q[j] + (refill_off)); \
        }                                                                       \
    } while (0)

// Renorm: pin lane max near 2^0; base clamped to >= (left base - 48);
// zero lanes adopt left base. Scales are exact powers of two.
#define RENORM()                                                                \
    do {                                                                        \
        u32 m = __float_as_uint(S[0]);                                          \
        _Pragma("unroll")                                                       \
        for (int j = 1; j < 8; j++) m = max(m, __float_as_uint(S[j]));          \
        const int e = (int)(m >> 23);                                           \
        const int d = min(127, max(-126, 127 - e));                             \
        const int tb = (m == 0u) ? base : (base - d);                           \
        const int bp = __shfl_up_sync(0xffffffffu, tb, 1);                      \
        int nb = tb;                                                            \
        if (lane > 0) nb = (m == 0u) ? bp : max(tb, bp - 48);                   \
        const int sh = base - nb;                                               \
        const int s1 = min(127, max(-126, sh));                                 \
        const int s2 = min(127, max(-126, sh - s1));                            \
        const float f1 = p2f(s1), f2 = p2f(s2);                                 \
        _Pragma("unroll")                                                       \
        for (int j = 0; j < 8; j++) S[j] = S[j] * f1 * f2;                      \
        base = nb;                                                              \
        const int bpf = __shfl_up_sync(0xffffffffu, base, 1);                   \
        const int diff = bpf - base;                                            \
        int d1 = diff >> 1;                                                     \
        int d2 = diff - d1;                                                     \
        d1 = min(126, max(-126, d1)); d2 = min(126, max(-126, d2));             \
        c1 = (lane == 0) ? 0.f : p2f(d1);                                       \
        c2 = p2f(d2);                                                           \
    } while (0)

    // Main: 249 blocks of 8 steps, t = 1 .. 1992. q base = tb_block - 1.
    for (int blk = 0; blk < 249; blk++) {
#pragma unroll
        for (int kk = 0; kk < 8; kk++) {
            const int slot = (kk + 1) & 7;
            STEP(slot, (kk + 9) * C, true);
            if (kk == 3 || kk == 7) RENORM();
        }
#pragma unroll
        for (int j = 0; j < 8; j++) q[j] += 8 * C;
    }

    // Tail: t = 1993 .. 1999 (7 steps).
#pragma unroll
    for (int kk = 0; kk < 7; kk++) {
        STEP(kk + 1, 0, false);
        if (kk == 3) RENORM();
    }

    // reduce correction across lanes (deterministic tree)
#pragma unroll
    for (int o = 16; o; o >>= 1) corr += __shfl_xor_sync(0xffffffffu, corr, o);

    if (lane == 31) {
        const float alpha2 = lg2f(S[7]) + (float)base;     // raw log2 alpha
        g_bloss[b] = (corr - alpha2) * LN2_F;              // normalize, nats
    }
#undef STEP
#undef RENORM
}

// ---------------------------------------------------------------------------
// K3: deterministic mean over the batch.
// ---------------------------------------------------------------------------
__global__ __launch_bounds__(128) void reduce_kernel(float* __restrict__ out) {
    const int i = threadIdx.x;
    float v = g_bloss[i];
#pragma unroll
    for (int o = 16; o; o >>= 1) v += __shfl_xor_sync(0xffffffffu, v, o);
    __shared__ float ws[4];
    if ((i & 31) == 0) ws[i >> 5] = v;
    __syncthreads();
    if (i == 0) out[0] = (ws[0] + ws[1] + ws[2] + ws[3]) * (1.0f / (float)B);
}

// ---------------------------------------------------------------------------
extern "C" void kernel_launch(void* const* d_in, const int* in_sizes, int n_in,
                              void* d_out, int out_size) {
    const float* x = (const float*)d_in[0];   // [B, T, C] float32
    const int* tg = (const int*)d_in[1];      // [B, L] int32
    float* out = (float*)d_out;

    (void)in_sizes; (void)n_in; (void)out_size;

    prob_kernel<<<(B * T) / 32, 256>>>(x);
    recur_kernel<<<B, 32>>>(tg);
    reduce_kernel<<<1, 128>>>(out);
}

// round 9
// speedup vs baseline: 9.4346x; 1.1734x over previous
#include <cuda_runtime.h>
#include <stdint.h>

// Transducer loss: unnormalized linear-domain fp32 recurrence.
// R9: recurrence gathers moved off the LDG path — rows staged cooperatively
// (1 coalesced LDG.64/row warp-wide, 8 rows per macro, 2-macro prefetch) into
// a smem ring; per-label gathers are LDS [R+imm] with time-invariant addresses.
// Renorm numerics identical to R8 (per-lane pow2 bases, -48 bounded diff).

#define INV_LN2 1.44269504088896340736f
#define LN2_F   0.69314718055994530942f

static constexpr int B  = 128;
static constexpr int T  = 2000;
static constexpr int C  = 62;
static constexpr int L  = 256;

typedef unsigned int u32;

__device__ float g_prob[B * T * C + 16 * C];  // raw 2^(x/ln2), padded
__device__ float g_lgs[B * T];                // log2 of per-row sum
__device__ float g_bloss[B];

static __device__ __forceinline__ float ex2f(float x) {
    float y; asm("ex2.approx.ftz.f32 %0, %1;" : "=f"(y) : "f"(x)); return y;
}
static __device__ __forceinline__ float lg2f(float x) {
    float y; asm("lg2.approx.ftz.f32 %0, %1;" : "=f"(y) : "f"(x)); return y;
}
static __device__ __forceinline__ float p2f(int e) {   // 2^e, e in [-126,127]
    return __uint_as_float((u32)(127 + e) << 23);
}

// ---------------------------------------------------------------------------
// K1: streaming map + fused rowsums, float4 vectorized. (At LTS cap already.)
// ---------------------------------------------------------------------------
__global__ __launch_bounds__(256) void prob_kernel(const float* __restrict__ x) {
    __shared__ float sp[32 * C];
    const long base = (long)blockIdx.x * (32 * C);
    const float4* xv = (const float4*)(x + base);
    float4* pv = (float4*)(g_prob + base);

#pragma unroll
    for (int it = 0; it < 2; it++) {
        const int i = threadIdx.x + it * 256;
        if (i < (32 * C) / 4) {
            const float4 v = __ldg(xv + i);
            float4 p;
            p.x = ex2f(v.x * INV_LN2);
            p.y = ex2f(v.y * INV_LN2);
            p.z = ex2f(v.z * INV_LN2);
            p.w = ex2f(v.w * INV_LN2);
            pv[i] = p;
            *(float4*)(sp + 4 * i) = p;
        }
    }
    __syncthreads();

    const int r = threadIdx.x >> 3;
    const int k = threadIdx.x & 7;
    float s = 0.f;
    const int off = r * C + k * 8;
#pragma unroll
    for (int i = 0; i < 8; i++)
        if (k * 8 + i < C) s += sp[off + i];
    s += __shfl_xor_sync(0xffffffffu, s, 4);
    s += __shfl_xor_sync(0xffffffffu, s, 2);
    s += __shfl_xor_sync(0xffffffffu, s, 1);
    if (k == 0) g_lgs[blockIdx.x * 32 + r] = lg2f(s);
}

// ---------------------------------------------------------------------------
// K2: the recurrence. One warp per batch. S[j] = label 8*lane+j.
// ---------------------------------------------------------------------------
__global__ __launch_bounds__(32, 1) void recur_kernel(const int* __restrict__ tg) {
    const int b = blockIdx.x;
    const int lane = threadIdx.x;

    __shared__ float sbuf[2][8][64];   // [buf][slot][padded row]

    // ---- fused normalization-correction partial sum (off critical path) ----
    float corr = 0.f;
    {
        const float4* lgv = (const float4*)(g_lgs + b * T);
#pragma unroll 4
        for (int i = lane; i < T / 4; i += 32) {
            const float4 v = __ldg(lgv + i);
            corr += (v.x + v.y) + (v.z + v.w);
        }
    }

    const float* prow = g_prob + (long)b * T * C;

    // Time-invariant gather addresses (smem base + target column).
    float* ap[8];
    int tgt0 = 0;
#pragma unroll
    for (int j = 0; j < 8; j++) {
        const int tc = __ldg(tg + b * L + lane * 8 + j);
        if (j == 0) tgt0 = tc;
        ap[j] = &sbuf[0][0][tc];
    }

    // ---- prologue: stage macro 0 (t=1..8) into buf0, load macro 1 into regs
    float2 R[8];
#pragma unroll
    for (int s = 0; s < 8; s++)
        R[s] = *(const float2*)(prow + (1 + s) * C + 2 * lane);
#pragma unroll
    for (int s = 0; s < 8; s++)
        *(float2*)&sbuf[0][s][2 * lane] = R[s];
#pragma unroll
    for (int s = 0; s < 8; s++)
        R[s] = *(const float2*)(prow + (9 + s) * C + 2 * lane);
    const float2* pr = (const float2*)(prow + 17 * C + 2 * lane);
    __syncwarp();

    float G0[8], G1[8];
#pragma unroll
    for (int j = 0; j < 8; j++) G0[j] = ap[j][0];    // t=1 gathers (buf0 slot0)

    float S[8];
#pragma unroll
    for (int j = 0; j < 8; j++) S[j] = 0.f;
    if (lane == 0) S[0] = __ldg(prow + tgt0);        // t = 0 init

    int base = 0;                            // true = S * 2^base, per lane
    float c1 = (lane == 0) ? 0.f : 1.f;
    float c2 = 1.f;

#define STEP(GC, GN, NW)                                                       \
    do {                                                                        \
        float cr = __shfl_up_sync(0xffffffffu, S[7], 1) * c1 * c2;              \
        S[7] = (S[7] + S[6]) * GC[7];  S[6] = (S[6] + S[5]) * GC[6];            \
        S[5] = (S[5] + S[4]) * GC[5];  S[4] = (S[4] + S[3]) * GC[4];            \
        S[3] = (S[3] + S[2]) * GC[3];  S[2] = (S[2] + S[1]) * GC[2];            \
        S[1] = (S[1] + S[0]) * GC[1];  S[0] = (S[0] + cr) * GC[0];              \
        _Pragma("unroll")                                                       \
        for (int j = 0; j < 8; j++) GN[j] = ap[j][NW];                          \
    } while (0)

#define STEP_NP(GC)                                                            \
    do {                                                                        \
        float cr = __shfl_up_sync(0xffffffffu, S[7], 1) * c1 * c2;              \
        S[7] = (S[7] + S[6]) * GC[7];  S[6] = (S[6] + S[5]) * GC[6];            \
        S[5] = (S[5] + S[4]) * GC[5];  S[4] = (S[4] + S[3]) * GC[4];            \
        S[3] = (S[3] + S[2]) * GC[3];  S[2] = (S[2] + S[1]) * GC[2];            \
        S[1] = (S[1] + S[0]) * GC[1];  S[0] = (S[0] + cr) * GC[0];              \
    } while (0)

// Renorm: bit-identical numerics to R8 (pin 2^0, -48 bounded diff, adoption).
#define RENORM()                                                                \
    do {                                                                        \
        u32 m = __float_as_uint(S[0]);                                          \
        _Pragma("unroll")                                                       \
        for (int j = 1; j < 8; j++) m = max(m, __float_as_uint(S[j]));          \
        const int e = (int)(m >> 23);                                           \
        const int d = min(127, max(-126, 127 - e));                             \
        const int tb = (m == 0u) ? base : (base - d);                           \
        const int bp = __shfl_up_sync(0xffffffffu, tb, 1);                      \
        int nb = tb;                                                            \
        if (lane > 0) nb = (m == 0u) ? bp : max(tb, bp - 48);                   \
        const int sh = base - nb;                                               \
        const int s1 = min(127, max(-126, sh));                                 \
        const int s2 = min(127, max(-126, sh - s1));                            \
        const float f1 = p2f(s1), f2 = p2f(s2);                                 \
        _Pragma("unroll")                                                       \
        for (int j = 0; j < 8; j++) S[j] = S[j] * f1 * f2;                      \
        base = nb;                                                              \
        const int bpf = __shfl_up_sync(0xffffffffu, base, 1);                   \
        const int diff = bpf - base;                                            \
        int d1 = diff >> 1;                                                     \
        int d2 = diff - d1;                                                     \
        d1 = min(126, max(-126, d1)); d2 = min(126, max(-126, d2));             \
        c1 = (lane == 0) ? 0.f : p2f(d1);                                       \
        c2 = p2f(d2);                                                           \
    } while (0)

// One macro-iteration: STS next macro's rows, LDG macro+2, 8 steps + 2 renorms.
// mbuf = consume buffer (compile-time), steps t = 8m+1 .. 8m+8.
#define MACRO(mbuf)                                                             \
    do {                                                                        \
        _Pragma("unroll")                                                       \
        for (int s = 0; s < 8; s++)                                             \
            *(float2*)&sbuf[1 - (mbuf)][s][2 * lane] = R[s];                    \
        _Pragma("unroll")                                                       \
        for (int s = 0; s < 8; s++) R[s] = __ldg(pr + s * 31);                  \
        pr += 248;                                                              \
        __syncwarp();                                                           \
        STEP(G0, G1, (mbuf) * 512 + 64);                                        \
        STEP(G1, G0, (mbuf) * 512 + 128);                                       \
        STEP(G0, G1, (mbuf) * 512 + 192);                                       \
        STEP(G1, G0, (mbuf) * 512 + 256); RENORM();                             \
        STEP(G0, G1, (mbuf) * 512 + 320);                                       \
        STEP(G1, G0, (mbuf) * 512 + 384);                                       \
        STEP(G0, G1, (mbuf) * 512 + 448);                                       \
        STEP(G1, G0, (1 - (mbuf)) * 512); RENORM();                             \
    } while (0)

    // Macros m = 0..248 cover t = 1..1992.
    for (int mm = 0; mm < 124; mm++) { MACRO(0); MACRO(1); }
    MACRO(0);   // m = 248

    // Tail: t = 1993..1999 (7 steps) from buf1 (written during m = 248).
    STEP(G0, G1, 512 + 64);
    STEP(G1, G0, 512 + 128);
    STEP(G0, G1, 512 + 192);
    STEP(G1, G0, 512 + 256); RENORM();
    STEP(G0, G1, 512 + 320);
    STEP(G1, G0, 512 + 384);
    STEP_NP(G0);

    // reduce correction across lanes (deterministic tree)
#pragma unroll
    for (int o = 16; o; o >>= 1) corr += __shfl_xor_sync(0xffffffffu, corr, o);

    if (lane == 31) {
        const float alpha2 = lg2f(S[7]) + (float)base;     // raw log2 alpha
        g_bloss[b] = (corr - alpha2) * LN2_F;              // normalize, nats
    }
#undef STEP
#undef STEP_NP
#undef RENORM
#undef MACRO
}

// ---------------------------------------------------------------------------
// K3: deterministic mean over the batch.
// ---------------------------------------------------------------------------
__global__ __launch_bounds__(128) void reduce_kernel(float* __restrict__ out) {
    const int i = threadIdx.x;
    float v = g_bloss[i];
#pragma unroll
    for (int o = 16; o; o >>= 1) v += __shfl_xor_sync(0xffffffffu, v, o);
    __shared__ float ws[4];
    if ((i & 31) == 0) ws[i >> 5] = v;
    __syncthreads();
    if (i == 0) out[0] = (ws[0] + ws[1] + ws[2] + ws[3]) * (1.0f / (float)B);
}

// ---------------------------------------------------------------------------
extern "C" void kernel_launch(void* const* d_in, const int* in_sizes, int n_in,
                              void* d_out, int out_size) {
    const float* x = (const float*)d_in[0];   // [B, T, C] float32
    const int* tg = (const int*)d_in[1];      // [B, L] int32
    float* out = (float*)d_out;

    (void)in_sizes; (void)n_in; (void)out_size;

    prob_kernel<<<(B * T) / 32, 256>>>(x);
    recur_kernel<<<B, 32>>>(tg);
    reduce_kernel<<<1, 128>>>(out);
}

// round 10
// speedup vs baseline: 11.9418x; 1.2658x over previous
#include <cuda_runtime.h>
#include <stdint.h>

// Transducer loss: unnormalized linear-domain fp32 recurrence.
// R10: LDG prefetch deepened to 2 macros (16 steps ~650cyc > DRAM lat) via two
// parity-pinned register row-sets. Smem-staged gathers + renorm numerics
// bit-identical to R9.

#define INV_LN2 1.44269504088896340736f
#define LN2_F   0.69314718055994530942f

static constexpr int B  = 128;
static constexpr int T  = 2000;
static constexpr int C  = 62;
static constexpr int L  = 256;

typedef unsigned int u32;

__device__ float g_prob[B * T * C + 32 * C];  // padded 32 rows for prefetch overshoot
__device__ float g_lgs[B * T];                // log2 of per-row sum
__device__ float g_bloss[B];

static __device__ __forceinline__ float ex2f(float x) {
    float y; asm("ex2.approx.ftz.f32 %0, %1;" : "=f"(y) : "f"(x)); return y;
}
static __device__ __forceinline__ float lg2f(float x) {
    float y; asm("lg2.approx.ftz.f32 %0, %1;" : "=f"(y) : "f"(x)); return y;
}
static __device__ __forceinline__ float p2f(int e) {   // 2^e, e in [-126,127]
    return __uint_as_float((u32)(127 + e) << 23);
}

// ---------------------------------------------------------------------------
// K1: streaming map + fused rowsums, float4 vectorized. (At LTS cap.)
// ---------------------------------------------------------------------------
__global__ __launch_bounds__(256) void prob_kernel(const float* __restrict__ x) {
    __shared__ float sp[32 * C];
    const long base = (long)blockIdx.x * (32 * C);
    const float4* xv = (const float4*)(x + base);
    float4* pv = (float4*)(g_prob + base);

#pragma unroll
    for (int it = 0; it < 2; it++) {
        const int i = threadIdx.x + it * 256;
        if (i < (32 * C) / 4) {
            const float4 v = __ldg(xv + i);
            float4 p;
            p.x = ex2f(v.x * INV_LN2);
            p.y = ex2f(v.y * INV_LN2);
            p.z = ex2f(v.z * INV_LN2);
            p.w = ex2f(v.w * INV_LN2);
            pv[i] = p;
            *(float4*)(sp + 4 * i) = p;
        }
    }
    __syncthreads();

    const int r = threadIdx.x >> 3;
    const int k = threadIdx.x & 7;
    float s = 0.f;
    const int off = r * C + k * 8;
#pragma unroll
    for (int i = 0; i < 8; i++)
        if (k * 8 + i < C) s += sp[off + i];
    s += __shfl_xor_sync(0xffffffffu, s, 4);
    s += __shfl_xor_sync(0xffffffffu, s, 2);
    s += __shfl_xor_sync(0xffffffffu, s, 1);
    if (k == 0) g_lgs[blockIdx.x * 32 + r] = lg2f(s);
}

// ---------------------------------------------------------------------------
// K2: the recurrence. One warp per batch. S[j] = label 8*lane+j.
// ---------------------------------------------------------------------------
__global__ __launch_bounds__(32, 1) void recur_kernel(const int* __restrict__ tg) {
    const int b = blockIdx.x;
    const int lane = threadIdx.x;

    __shared__ float sbuf[2][8][64];   // [buf][slot][padded row]

    const float* prow = g_prob + (long)b * T * C;

    // Time-invariant gather addresses (smem base + target column).
    float* ap[8];
    int tgt0 = 0;
#pragma unroll
    for (int j = 0; j < 8; j++) {
        const int tc = __ldg(tg + b * L + lane * 8 + j);
        if (j == 0) tgt0 = tc;
        ap[j] = &sbuf[0][0][tc];
    }

    // ---- prologue ----
    // stage macro 0 (t=1..8) into buf0; RA <- macro1 (t=9..16, odd-parity set);
    // RB <- macro2 (t=17..24, even-parity set); pr points at macro3.
    float2 RA[8], RB[8];
#pragma unroll
    for (int s = 0; s < 8; s++)
        RA[s] = *(const float2*)(prow + (1 + s) * C + 2 * lane);
#pragma unroll
    for (int s = 0; s < 8; s++)
        *(float2*)&sbuf[0][s][2 * lane] = RA[s];
#pragma unroll
    for (int s = 0; s < 8; s++)
        RA[s] = *(const float2*)(prow + (9 + s) * C + 2 * lane);
#pragma unroll
    for (int s = 0; s < 8; s++)
        RB[s] = *(const float2*)(prow + (17 + s) * C + 2 * lane);
    const float2* pr = (const float2*)(prow + 25 * C + 2 * lane);
    __syncwarp();

    // ---- fused normalization-correction partial sum (off critical path) ----
    float corr = 0.f;
    {
        const float4* lgv = (const float4*)(g_lgs + b * T);
#pragma unroll 4
        for (int i = lane; i < T / 4; i += 32) {
            const float4 v = __ldg(lgv + i);
            corr += (v.x + v.y) + (v.z + v.w);
        }
    }

    float G0[8], G1[8];
#pragma unroll
    for (int j = 0; j < 8; j++) G0[j] = ap[j][0];    // t=1 gathers (buf0 slot0)

    float S[8];
#pragma unroll
    for (int j = 0; j < 8; j++) S[j] = 0.f;
    if (lane == 0) S[0] = __ldg(prow + tgt0);        // t = 0 init

    int base = 0;                            // true = S * 2^base, per lane
    float c1 = (lane == 0) ? 0.f : 1.f;
    float c2 = 1.f;

#define STEP(GC, GN, NW)                                                       \
    do {                                                                        \
        float cr = __shfl_up_sync(0xffffffffu, S[7], 1) * c1 * c2;              \
        S[7] = (S[7] + S[6]) * GC[7];  S[6] = (S[6] + S[5]) * GC[6];            \
        S[5] = (S[5] + S[4]) * GC[5];  S[4] = (S[4] + S[3]) * GC[4];            \
        S[3] = (S[3] + S[2]) * GC[3];  S[2] = (S[2] + S[1]) * GC[2];            \
        S[1] = (S[1] + S[0]) * GC[1];  S[0] = (S[0] + cr) * GC[0];              \
        _Pragma("unroll")                                                       \
        for (int j = 0; j < 8; j++) GN[j] = ap[j][NW];                          \
    } while (0)

#define STEP_NP(GC)                                                            \
    do {                                                                        \
        float cr = __shfl_up_sync(0xffffffffu, S[7], 1) * c1 * c2;              \
        S[7] = (S[7] + S[6]) * GC[7];  S[6] = (S[6] + S[5]) * GC[6];            \
        S[5] = (S[5] + S[4]) * GC[5];  S[4] = (S[4] + S[3]) * GC[4];            \
        S[3] = (S[3] + S[2]) * GC[3];  S[2] = (S[2] + S[1]) * GC[2];            \
        S[1] = (S[1] + S[0]) * GC[1];  S[0] = (S[0] + cr) * GC[0];              \
    } while (0)

// Renorm: bit-identical numerics to R8/R9 (pin 2^0, -48 bounded diff, adoption).
#define RENORM()                                                                \
    do {                                                                        \
        u32 m = __float_as_uint(S[0]);                                          \
        _Pragma("unroll")                                                       \
        for (int j = 1; j < 8; j++) m = max(m, __float_as_uint(S[j]));          \
        const int e = (int)(m >> 23);                                           \
        const int d = min(127, max(-126, 127 - e));                             \
        const int tb = (m == 0u) ? base : (base - d);                           \
        const int bp = __shfl_up_sync(0xffffffffu, tb, 1);                      \
        int nb = tb;                                                            \
        if (lane > 0) nb = (m == 0u) ? bp : max(tb, bp - 48);                   \
        const int sh = base - nb;                                               \
        const int s1 = min(127, max(-126, sh));                                 \
        const int s2 = min(127, max(-126, sh - s1));                            \
        const float f1 = p2f(s1), f2 = p2f(s2);                                 \
        _Pragma("unroll")                                                       \
        for (int j = 0; j < 8; j++) S[j] = S[j] * f1 * f2;                      \
        base = nb;                                                              \
        const int bpf = __shfl_up_sync(0xffffffffu, base, 1);                   \
        const int diff = bpf - base;                                            \
        int d1 = diff >> 1;                                                     \
        int d2 = diff - d1;                                                     \
        d1 = min(126, max(-126, d1)); d2 = min(126, max(-126, d2));             \
        c1 = (lane == 0) ? 0.f : p2f(d1);                                       \
        c2 = p2f(d2);                                                           \
    } while (0)

// One macro-iteration (macro m, mbuf = m&1, RS = register set of parity m+1):
// STS macro m+1 rows (loaded 2 macros ago), LDG macro m+3 into same set,
// 8 steps + 2 renorms consuming buf[mbuf].
#define MACRO(mbuf, RS)                                                         \
    do {                                                                        \
        _Pragma("unroll")                                                       \
        for (int s = 0; s < 8; s++)                                             \
            *(float2*)&sbuf[1 - (mbuf)][s][2 * lane] = RS[s];                   \
        _Pragma("unroll")                                                       \
        for (int s = 0; s < 8; s++) RS[s] = __ldg(pr + s * 31);                 \
        pr += 248;                                                              \
        __syncwarp();                                                           \
        STEP(G0, G1, (mbuf) * 512 + 64);                                        \
        STEP(G1, G0, (mbuf) * 512 + 128);                                       \
        STEP(G0, G1, (mbuf) * 512 + 192);                                       \
        STEP(G1, G0, (mbuf) * 512 + 256); RENORM();                             \
        STEP(G0, G1, (mbuf) * 512 + 320);                                       \
        STEP(G1, G0, (mbuf) * 512 + 384);                                       \
        STEP(G0, G1, (mbuf) * 512 + 448);                                       \
        STEP(G1, G0, (1 - (mbuf)) * 512); RENORM();                             \
    } while (0)

    // Macros m = 0..248 cover t = 1..1992. Even m consumes buf0 + set RA
    // (RA holds odd macros m+1), odd m consumes buf1 + set RB.
    for (int mm = 0; mm < 124; mm++) { MACRO(0, RA); MACRO(1, RB); }
    MACRO(0, RA);   // m = 248 (STS RA = macro 249 rows t=1993..2000)

    // Tail: t = 1993..1999 (7 steps) from buf1.
    STEP(G0, G1, 512 + 64);
    STEP(G1, G0, 512 + 128);
    STEP(G0, G1, 512 + 192);
    STEP(G1, G0, 512 + 256); RENORM();
    STEP(G0, G1, 512 + 320);
    STEP(G1, G0, 512 + 384);
    STEP_NP(G0);

    // reduce correction across lanes (deterministic tree)
#pragma unroll
    for (int o = 16; o; o >>= 1) corr += __shfl_xor_sync(0xffffffffu, corr, o);

    if (lane == 31) {
        const float alpha2 = lg2f(S[7]) + (float)base;     // raw log2 alpha
        g_bloss[b] = (corr - alpha2) * LN2_F;              // normalize, nats
    }
#undef STEP
#undef STEP_NP
#undef RENORM
#undef MACRO
}

// ---------------------------------------------------------------------------
// K3: deterministic mean over the batch.
// ---------------------------------------------------------------------------
__global__ __launch_bounds__(128) void reduce_kernel(float* __restrict__ out) {
    const int i = threadIdx.x;
    float v = g_bloss[i];
#pragma unroll
    for (int o = 16; o; o >>= 1) v += __shfl_xor_sync(0xffffffffu, v, o);
    __shared__ float ws[4];
    if ((i & 31) == 0) ws[i >> 5] = v;
    __syncthreads();
    if (i == 0) out[0] = (ws[0] + ws[1] + ws[2] + ws[3]) * (1.0f / (float)B);
}

// ---------------------------------------------------------------------------
extern "C" void kernel_launch(void* const* d_in, const int* in_sizes, int n_in,
                              void* d_out, int out_size) {
    const float* x = (const float*)d_in[0];   // [B, T, C] float32
    const int* tg = (const int*)d_in[1];      // [B, L] int32
    float* out = (float*)d_out;

    (void)in_sizes; (void)n_in; (void)out_size;

    prob_kernel<<<(B * T) / 32, 256>>>(x);
    recur_kernel<<<B, 32>>>(tg);
    reduce_kernel<<<1, 128>>>(out);
}

// round 11
// speedup vs baseline: 12.2052x; 1.0221x over previous
#include <cuda_runtime.h>
#include <stdint.h>

// Transducer loss: unnormalized linear-domain fp32 recurrence.
// R11: renorm split into COMPUTE (contains both shfls) and APPLY, deferred by
// 2 steps so the serial renorm chain overlaps step work. Macros widened to 16
// steps with a single register row-set (LDG->consume = 16 steps).

#define INV_LN2 1.44269504088896340736f
#define LN2_F   0.69314718055994530942f

static constexpr int B  = 128;
static constexpr int T  = 2000;
static constexpr int C  = 62;
static constexpr int L  = 256;

typedef unsigned int u32;

__device__ float g_prob[B * T * C + 32 * C];  // padded for prefetch overshoot (to t=2016)
__device__ float g_lgs[B * T];                // log2 of per-row sum
__device__ float g_bloss[B];

static __device__ __forceinline__ float ex2f(float x) {
    float y; asm("ex2.approx.ftz.f32 %0, %1;" : "=f"(y) : "f"(x)); return y;
}
static __device__ __forceinline__ float lg2f(float x) {
    float y; asm("lg2.approx.ftz.f32 %0, %1;" : "=f"(y) : "f"(x)); return y;
}
static __device__ __forceinline__ float p2f(int e) {   // 2^e, e in [-126,127]
    return __uint_as_float((u32)(127 + e) << 23);
}

// ---------------------------------------------------------------------------
// K1: streaming map + fused rowsums, float4 vectorized. (At LTS cap.)
// ---------------------------------------------------------------------------
__global__ __launch_bounds__(256) void prob_kernel(const float* __restrict__ x) {
    __shared__ float sp[32 * C];
    const long base = (long)blockIdx.x * (32 * C);
    const float4* xv = (const float4*)(x + base);
    float4* pv = (float4*)(g_prob + base);

#pragma unroll
    for (int it = 0; it < 2; it++) {
        const int i = threadIdx.x + it * 256;
        if (i < (32 * C) / 4) {
            const float4 v = __ldg(xv + i);
            float4 p;
            p.x = ex2f(v.x * INV_LN2);
            p.y = ex2f(v.y * INV_LN2);
            p.z = ex2f(v.z * INV_LN2);
            p.w = ex2f(v.w * INV_LN2);
            pv[i] = p;
            *(float4*)(sp + 4 * i) = p;
        }
    }
    __syncthreads();

    const int r = threadIdx.x >> 3;
    const int k = threadIdx.x & 7;
    float s = 0.f;
    const int off = r * C + k * 8;
#pragma unroll
    for (int i = 0; i < 8; i++)
        if (k * 8 + i < C) s += sp[off + i];
    s += __shfl_xor_sync(0xffffffffu, s, 4);
    s += __shfl_xor_sync(0xffffffffu, s, 2);
    s += __shfl_xor_sync(0xffffffffu, s, 1);
    if (k == 0) g_lgs[blockIdx.x * 32 + r] = lg2f(s);
}

// ---------------------------------------------------------------------------
// K2: the recurrence. One warp per batch. S[j] = label 8*lane+j.
// ---------------------------------------------------------------------------
__global__ __launch_bounds__(32, 1) void recur_kernel(const int* __restrict__ tg) {
    const int b = blockIdx.x;
    const int lane = threadIdx.x;

    __shared__ float sbuf[2][16][64];   // [buf][slot][padded row]

    const float* prow = g_prob + (long)b * T * C;

    // Time-invariant gather addresses.
    float* ap[8];
    int tgt0 = 0;
#pragma unroll
    for (int j = 0; j < 8; j++) {
        const int tc = __ldg(tg + b * L + lane * 8 + j);
        if (j == 0) tgt0 = tc;
        ap[j] = &sbuf[0][0][tc];
    }

    // ---- prologue: stage macro0 (t=1..16) into buf0; R <- macro1 (t=17..32)
    float2 R[16];
#pragma unroll
    for (int s = 0; s < 16; s++)
        R[s] = *(const float2*)(prow + (1 + s) * C + 2 * lane);
#pragma unroll
    for (int s = 0; s < 16; s++)
        *(float2*)&sbuf[0][s][2 * lane] = R[s];
#pragma unroll
    for (int s = 0; s < 16; s++)
        R[s] = *(const float2*)(prow + (17 + s) * C + 2 * lane);
    const float2* pr = (const float2*)(prow + 33 * C + 2 * lane);
    __syncwarp();

    // ---- fused normalization-correction partial sum (off critical path) ----
    float corr = 0.f;
    {
        const float4* lgv = (const float4*)(g_lgs + b * T);
#pragma unroll 4
        for (int i = lane; i < T / 4; i += 32) {
            const float4 v = __ldg(lgv + i);
            corr += (v.x + v.y) + (v.z + v.w);
        }
    }

    float G0[8], G1[8];
#pragma unroll
    for (int j = 0; j < 8; j++) G0[j] = ap[j][0];    // t=1 gathers

    float S[8];
#pragma unroll
    for (int j = 0; j < 8; j++) S[j] = 0.f;
    if (lane == 0) S[0] = __ldg(prow + tgt0);        // t = 0 init

    int base = 0;                            // true = S * 2^base, per lane
    float c1 = (lane == 0) ? 0.f : 1.f;
    float c2 = 1.f;
    // pending renorm state (COMPUTE -> APPLY pipeline)
    float pf1 = 1.f, pf2 = 1.f, pc1 = c1, pc2 = 1.f;
    int pnb = 0;

#define STEP(GC, GN, NW)                                                       \
    do {                                                                        \
        float cr = __shfl_up_sync(0xffffffffu, S[7], 1) * c1 * c2;              \
        S[7] = (S[7] + S[6]) * GC[7];  S[6] = (S[6] + S[5]) * GC[6];            \
        S[5] = (S[5] + S[4]) * GC[5];  S[4] = (S[4] + S[3]) * GC[4];            \
        S[3] = (S[3] + S[2]) * GC[3];  S[2] = (S[2] + S[1]) * GC[2];            \
        S[1] = (S[1] + S[0]) * GC[1];  S[0] = (S[0] + cr) * GC[0];              \
        _Pragma("unroll")                                                       \
        for (int j = 0; j < 8; j++) GN[j] = ap[j][NW];                          \
    } while (0)

#define STEP_NP(GC)                                                            \
    do {                                                                        \
        float cr = __shfl_up_sync(0xffffffffu, S[7], 1) * c1 * c2;              \
        S[7] = (S[7] + S[6]) * GC[7];  S[6] = (S[6] + S[5]) * GC[6];            \
        S[5] = (S[5] + S[4]) * GC[5];  S[4] = (S[4] + S[3]) * GC[4];            \
        S[3] = (S[3] + S[2]) * GC[3];  S[2] = (S[2] + S[1]) * GC[2];            \
        S[1] = (S[1] + S[0]) * GC[1];  S[0] = (S[0] + cr) * GC[0];              \
    } while (0)

// COMPUTE: derive pending scale/base/carry-factors from current S. Contains
// both shfls; its latency overlaps the next 2 STEPs (which keep the old
// representation -> carries stay consistent until APPLY).
#define RCOMP()                                                                 \
    do {                                                                        \
        u32 m = __float_as_uint(S[0]);                                          \
        _Pragma("unroll")                                                       \
        for (int j = 1; j < 8; j++) m = max(m, __float_as_uint(S[j]));          \
        const int e = (int)(m >> 23);                                           \
        const int d = min(127, max(-126, 127 - e));                             \
        const int tb = (m == 0u) ? base : (base - d);                           \
        const int bp = __shfl_up_sync(0xffffffffu, tb, 1);                      \
        int nb = tb;                                                            \
        if (lane > 0) nb = (m == 0u) ? bp : max(tb, bp - 48);                   \
        const int sh = base - nb;                                               \
        const int s1 = min(127, max(-126, sh));                                 \
        const int s2 = min(127, max(-126, sh - s1));                            \
        pf1 = p2f(s1); pf2 = p2f(s2); pnb = nb;                                 \
        const int bpf = __shfl_up_sync(0xffffffffu, nb, 1);                     \
        const int diff = bpf - nb;                                              \
        int d1 = diff >> 1;                                                     \
        int d2 = diff - d1;                                                     \
        d1 = min(126, max(-126, d1)); d2 = min(126, max(-126, d2));             \
        pc1 = (lane == 0) ? 0.f : p2f(d1);                                      \
        pc2 = p2f(d2);                                                          \
    } while (0)

#define RAPPLY()                                                                \
    do {                                                                        \
        _Pragma("unroll")                                                       \
        for (int j = 0; j < 8; j++) S[j] = S[j] * pf1 * pf2;                    \
        base = pnb; c1 = pc1; c2 = pc2;                                         \
    } while (0)

// 16-step macro: STS macro m+1 rows, LDG macro m+2 into R, then 16 steps with
// renorm COMPUTE after steps 1,5,9,13 and APPLY after steps 3,7,11,15.
#define MACRO16(mbuf)                                                           \
    do {                                                                        \
        _Pragma("unroll")                                                       \
        for (int s = 0; s < 16; s++)                                            \
            *(float2*)&sbuf[1 - (mbuf)][s][2 * lane] = R[s];                    \
        _Pragma("unroll")                                                       \
        for (int s = 0; s < 16; s++) R[s] = __ldg(pr + s * 31);                 \
        pr += 16 * 31;                                                          \
        __syncwarp();                                                           \
        STEP(G0, G1, ((mbuf) * 16 + 1) * 64);                                   \
        STEP(G1, G0, ((mbuf) * 16 + 2) * 64);  RCOMP();                         \
        STEP(G0, G1, ((mbuf) * 16 + 3) * 64);                                   \
        STEP(G1, G0, ((mbuf) * 16 + 4) * 64);  RAPPLY();                        \
        STEP(G0, G1, ((mbuf) * 16 + 5) * 64);                                   \
        STEP(G1, G0, ((mbuf) * 16 + 6) * 64);  RCOMP();                         \
        STEP(G0, G1, ((mbuf) * 16 + 7) * 64);                                   \
        STEP(G1, G0, ((mbuf) * 16 + 8) * 64);  RAPPLY();                        \
        STEP(G0, G1, ((mbuf) * 16 + 9) * 64);                                   \
        STEP(G1, G0, ((mbuf) * 16 + 10) * 64); RCOMP();                         \
        STEP(G0, G1, ((mbuf) * 16 + 11) * 64);                                  \
        STEP(G1, G0, ((mbuf) * 16 + 12) * 64); RAPPLY();                        \
        STEP(G0, G1, ((mbuf) * 16 + 13) * 64);                                  \
        STEP(G1, G0, ((mbuf) * 16 + 14) * 64); RCOMP();                         \
        STEP(G0, G1, ((mbuf) * 16 + 15) * 64);                                  \
        STEP(G1, G0, ((1 - (mbuf)) * 16) * 64); RAPPLY();                       \
    } while (0)

    // Macros m = 0..123 cover t = 1..1984 (even count -> parity pairs).
    for (int mm = 0; mm < 62; mm++) { MACRO16(0); MACRO16(1); }

    // Tail: t = 1985..1999 (15 steps) from buf0 (written during macro 123).
    STEP(G0, G1, 1 * 64);
    STEP(G1, G0, 2 * 64);   RCOMP();
    STEP(G0, G1, 3 * 64);
    STEP(G1, G0, 4 * 64);   RAPPLY();
    STEP(G0, G1, 5 * 64);
    STEP(G1, G0, 6 * 64);   RCOMP();
    STEP(G0, G1, 7 * 64);
    STEP(G1, G0, 8 * 64);   RAPPLY();
    STEP(G0, G1, 9 * 64);
    STEP(G1, G0, 10 * 64);  RCOMP();
    STEP(G0, G1, 11 * 64);
    STEP(G1, G0, 12 * 64);  RAPPLY();
    STEP(G0, G1, 13 * 64);
    STEP(G1, G0, 14 * 64);
    STEP_NP(G0);

    // reduce correction across lanes (deterministic tree)
#pragma unroll
    for (int o = 16; o; o >>= 1) corr += __shfl_xor_sync(0xffffffffu, corr, o);

    if (lane == 31) {
        const float alpha2 = lg2f(S[7]) + (float)base;     // raw log2 alpha
        g_bloss[b] = (corr - alpha2) * LN2_F;              // normalize, nats
    }
#undef STEP
#undef STEP_NP
#undef RCOMP
#undef RAPPLY
#undef MACRO16
}

// ---------------------------------------------------------------------------
// K3: deterministic mean over the batch.
// ---------------------------------------------------------------------------
__global__ __launch_bounds__(128) void reduce_kernel(float* __restrict__ out) {
    const int i = threadIdx.x;
    float v = g_bloss[i];
#pragma unroll
    for (int o = 16; o; o >>= 1) v += __shfl_xor_sync(0xffffffffu, v, o);
    __shared__ float ws[4];
    if ((i & 31) == 0) ws[i >> 5] = v;
    __syncthreads();
    if (i == 0) out[0] = (ws[0] + ws[1] + ws[2] + ws[3]) * (1.0f / (float)B);
}

// ---------------------------------------------------------------------------
extern "C" void kernel_launch(void* const* d_in, const int* in_sizes, int n_in,
                              void* d_out, int out_size) {
    const float* x = (const float*)d_in[0];   // [B, T, C] float32
    const int* tg = (const int*)d_in[1];      // [B, L] int32
    float* out = (float*)d_out;

    (void)in_sizes; (void)n_in; (void)out_size;

    prob_kernel<<<(B * T) / 32, 256>>>(x);
    recur_kernel<<<B, 32>>>(tg);
    reduce_kernel<<<1, 128>>>(out);
}